// round 1
// baseline (speedup 1.0000x reference)
#include <cuda_runtime.h>
#include <cuda_bf16.h>
#include <math.h>

#define BATCH 16
#define SEQ   512
#define NI    32
#define NHEAD 8
#define NH    512
#define NO    64
#define MROWS (BATCH*SEQ)      // 8192
#define VDIM  (NHEAD*NI)       // 256
#define EPSV  1e-5f
#define SLOPE 0.05f
#define RS    32               // row splits for stats

// ---------------- scratch (no allocation allowed) ----------------
__device__ float g_V [(size_t)MROWS * VDIM];   // 8 MB
__device__ float g_Y1[(size_t)MROWS * NH];     // 16 MB
__device__ float g_Y2[(size_t)MROWS * NH];     // 16 MB
__device__ float g_Y3[(size_t)MROWS * NO];     // 2 MB
__device__ float g_pS [RS * NH];
__device__ float g_pS2[RS * NH];
__device__ float g_scale[NH];
__device__ float g_shift[NH];

// ---------------- kernel 1: V = gaussian-attention features ----------------
// one block per (b,n); 256 threads = (h in 0..7) x (i in 0..31)
__global__ void __launch_bounds__(256) compute_v_kernel(
    const float* __restrict__ x, const float* __restrict__ Q, float* __restrict__ V)
{
    const int bn  = blockIdx.x;          // b*SEQ + n
    const int b   = bn >> 9;
    const int n   = bn & 511;
    const int tid = threadIdx.x;
    const int h   = tid >> 5;
    const int i   = tid & 31;

    __shared__ float xs[64][33];   // padded: col reads and pos reads conflict-free
    __shared__ float ws[8][64];
    __shared__ float qs[8][4];     // qx,qy,qz,|q|^2

    if (tid < 8) {
        float a = Q[tid*3+0], bq = Q[tid*3+1], cq = Q[tid*3+2];
        qs[tid][0] = a; qs[tid][1] = bq; qs[tid][2] = cq;
        qs[tid][3] = a*a + bq*bq + cq*cq;
    }

    const float* xb = x + (size_t)b * SEQ * NI;
    const float pn0 = xb[n*NI+0], pn1 = xb[n*NI+1], pn2 = xb[n*NI+2];

    float acc = 0.f;

    for (int m0 = 0; m0 < SEQ; m0 += 64) {
        // stage 64x32 x-tile (coalesced)
        const float* src = xb + (size_t)m0 * NI;
        #pragma unroll
        for (int j = tid; j < 64*32; j += 256) {
            xs[j >> 5][j & 31] = src[j];
        }
        __syncthreads();

        // compute 8x64 weight tile: exp(-||pn - pm - Qh||^2)
        #pragma unroll
        for (int j = tid; j < 512; j += 256) {
            int hh = j >> 6, mm = j & 63;
            float dx = pn0 - xs[mm][0];
            float dy = pn1 - xs[mm][1];
            float dz = pn2 - xs[mm][2];
            float d2 = dx*dx + dy*dy + dz*dz;
            float dq = dx*qs[hh][0] + dy*qs[hh][1] + dz*qs[hh][2];
            ws[hh][mm] = __expf(-(d2 - 2.f*dq + qs[hh][3]));
        }
        __syncthreads();

        // MAC: acc += sum_m ws[h][m] * x[m][i]   (ws broadcast per warp)
        #pragma unroll 16
        for (int mm = 0; mm < 64; mm++) {
            acc = fmaf(ws[h][mm], xs[mm][i], acc);
        }
        __syncthreads();
    }

    if (i < 3) acc -= (i == 0 ? pn0 : (i == 1 ? pn1 : pn2));
    V[(size_t)bn * VDIM + tid] = acc;   // tid == h*32+i, layout (b,n,h,i)
}

// ---------------- kernel 2: GEMM  Y[m][c] = bias[c] + sum_k A[m][k]*W[c][k] ----------------
// A: MxK row-major, W: CxK row-major. Tiles 64x64x16, 256 threads, 4x4 per thread.
__global__ void __launch_bounds__(256) gemm_bias_kernel(
    const float* __restrict__ A, const float* __restrict__ W,
    const float* __restrict__ bias, float* __restrict__ Y,
    int M, int K, int C)
{
    __shared__ float As[16][68];
    __shared__ float Bs[16][68];

    const int tid = threadIdx.x;
    const int tx = tid & 15, ty = tid >> 4;
    const int m0 = blockIdx.y * 64;
    const int c0 = blockIdx.x * 64;
    const int lr = tid >> 2;          // 0..63
    const int lk = (tid & 3) * 4;     // 0,4,8,12

    float acc[4][4] = {};

    for (int k0 = 0; k0 < K; k0 += 16) {
        float4 av = *(const float4*)(A + (size_t)(m0 + lr) * K + k0 + lk);
        float4 bv = *(const float4*)(W + (size_t)(c0 + lr) * K + k0 + lk);
        As[lk+0][lr] = av.x; As[lk+1][lr] = av.y; As[lk+2][lr] = av.z; As[lk+3][lr] = av.w;
        Bs[lk+0][lr] = bv.x; Bs[lk+1][lr] = bv.y; Bs[lk+2][lr] = bv.z; Bs[lk+3][lr] = bv.w;
        __syncthreads();

        #pragma unroll
        for (int kk = 0; kk < 16; kk++) {
            float4 a = *(const float4*)&As[kk][ty*4];
            float4 bb = *(const float4*)&Bs[kk][tx*4];
            acc[0][0] = fmaf(a.x, bb.x, acc[0][0]); acc[0][1] = fmaf(a.x, bb.y, acc[0][1]);
            acc[0][2] = fmaf(a.x, bb.z, acc[0][2]); acc[0][3] = fmaf(a.x, bb.w, acc[0][3]);
            acc[1][0] = fmaf(a.y, bb.x, acc[1][0]); acc[1][1] = fmaf(a.y, bb.y, acc[1][1]);
            acc[1][2] = fmaf(a.y, bb.z, acc[1][2]); acc[1][3] = fmaf(a.y, bb.w, acc[1][3]);
            acc[2][0] = fmaf(a.z, bb.x, acc[2][0]); acc[2][1] = fmaf(a.z, bb.y, acc[2][1]);
            acc[2][2] = fmaf(a.z, bb.z, acc[2][2]); acc[2][3] = fmaf(a.z, bb.w, acc[2][3]);
            acc[3][0] = fmaf(a.w, bb.x, acc[3][0]); acc[3][1] = fmaf(a.w, bb.y, acc[3][1]);
            acc[3][2] = fmaf(a.w, bb.z, acc[3][2]); acc[3][3] = fmaf(a.w, bb.w, acc[3][3]);
        }
        __syncthreads();
    }

    float4 bb = *(const float4*)(bias + c0 + tx*4);
    #pragma unroll
    for (int r = 0; r < 4; r++) {
        float4 o;
        o.x = acc[r][0] + bb.x; o.y = acc[r][1] + bb.y;
        o.z = acc[r][2] + bb.z; o.w = acc[r][3] + bb.w;
        *(float4*)(Y + (size_t)(m0 + ty*4 + r) * C + c0 + tx*4) = o;
    }
}

// ---------------- kernel 3a: per-column partial sums ----------------
// grid (C/32, RS); block 256 = 8 rows x 32 cols
__global__ void __launch_bounds__(256) stats_partial_kernel(
    const float* __restrict__ Y, int M, int C, float* __restrict__ pS, float* __restrict__ pS2)
{
    const int tx = threadIdx.x & 31, ty = threadIdx.x >> 5;
    const int c = blockIdx.x * 32 + tx;
    const int rows = M / RS;
    const int rbeg = blockIdx.y * rows;

    float s = 0.f, s2 = 0.f;
    for (int r = rbeg + ty; r < rbeg + rows; r += 8) {
        float v = Y[(size_t)r * C + c];
        s += v; s2 = fmaf(v, v, s2);
    }
    __shared__ float ss[8][33], ss2[8][33];
    ss[ty][tx] = s; ss2[ty][tx] = s2;
    __syncthreads();
    if (ty == 0) {
        #pragma unroll
        for (int j = 1; j < 8; j++) { s += ss[j][tx]; s2 += ss2[j][tx]; }
        pS [blockIdx.y * C + c] = s;
        pS2[blockIdx.y * C + c] = s2;
    }
}

// ---------------- kernel 3b: finalize BN affine per column ----------------
// grid C blocks of 32 threads
__global__ void stats_final_kernel(
    const float* __restrict__ pS, const float* __restrict__ pS2,
    const float* __restrict__ g, const float* __restrict__ bt,
    int M, int C, float* __restrict__ scale, float* __restrict__ shift)
{
    const int c = blockIdx.x;
    const int j = threadIdx.x;
    float s  = pS [j * C + c];
    float s2 = pS2[j * C + c];
    #pragma unroll
    for (int off = 16; off > 0; off >>= 1) {
        s  += __shfl_down_sync(0xffffffffu, s,  off);
        s2 += __shfl_down_sync(0xffffffffu, s2, off);
    }
    if (j == 0) {
        float invM = 1.f / (float)M;
        float mean = s * invM;
        float var  = fmaf(-mean, mean, s2 * invM);
        float inv  = rsqrtf(var + EPSV);
        float sc   = g[c] * inv;
        scale[c] = sc;
        shift[c] = fmaf(-mean, sc, bt[c]);
    }
}

// ---------------- kernel 4: BN apply (+ optional leaky relu), float4 ----------------
template<bool LEAKY>
__global__ void __launch_bounds__(256) bnact_kernel(
    const float* __restrict__ Y, const float* __restrict__ scale,
    const float* __restrict__ shift, float* __restrict__ out, int total4, int C4)
{
    int idx = blockIdx.x * blockDim.x + threadIdx.x;
    if (idx >= total4) return;
    int c4 = idx % C4;
    float4 y  = ((const float4*)Y)[idx];
    float4 sc = ((const float4*)scale)[c4];
    float4 sh = ((const float4*)shift)[c4];
    float4 o;
    o.x = fmaf(y.x, sc.x, sh.x);
    o.y = fmaf(y.y, sc.y, sh.y);
    o.z = fmaf(y.z, sc.z, sh.z);
    o.w = fmaf(y.w, sc.w, sh.w);
    if (LEAKY) {
        o.x = o.x > 0.f ? o.x : o.x * SLOPE;
        o.y = o.y > 0.f ? o.y : o.y * SLOPE;
        o.z = o.z > 0.f ? o.z : o.z * SLOPE;
        o.w = o.w > 0.f ? o.w : o.w * SLOPE;
    }
    ((float4*)out)[idx] = o;
}

// ---------------- host ----------------
static void bn_layer(const float* Y, const float* g, const float* bt,
                     float* out, int C, bool leaky,
                     float* pS, float* pS2, float* scale, float* shift)
{
    stats_partial_kernel<<<dim3(C/32, RS), 256>>>(Y, MROWS, C, pS, pS2);
    stats_final_kernel<<<C, 32>>>(pS, pS2, g, bt, MROWS, C, scale, shift);
    int total4 = MROWS * C / 4;
    int blocks = (total4 + 255) / 256;
    if (leaky)
        bnact_kernel<true ><<<blocks, 256>>>(Y, scale, shift, out, total4, C/4);
    else
        bnact_kernel<false><<<blocks, 256>>>(Y, scale, shift, out, total4, C/4);
}

extern "C" void kernel_launch(void* const* d_in, const int* in_sizes, int n_in,
                              void* d_out, int out_size)
{
    const float* x   = (const float*)d_in[0];
    const float* Q   = (const float*)d_in[1];
    const float* W1  = (const float*)d_in[2];
    const float* b1  = (const float*)d_in[3];
    const float* g1  = (const float*)d_in[4];
    const float* bt1 = (const float*)d_in[5];
    const float* W2  = (const float*)d_in[6];
    const float* b2  = (const float*)d_in[7];
    const float* g2  = (const float*)d_in[8];
    const float* bt2 = (const float*)d_in[9];
    const float* W3  = (const float*)d_in[10];
    const float* b3  = (const float*)d_in[11];
    const float* g3  = (const float*)d_in[12];
    const float* bt3 = (const float*)d_in[13];
    float* out = (float*)d_out;

    float *V, *Y1, *Y2, *Y3, *pS, *pS2, *scale, *shift;
    cudaGetSymbolAddress((void**)&V,     g_V);
    cudaGetSymbolAddress((void**)&Y1,    g_Y1);
    cudaGetSymbolAddress((void**)&Y2,    g_Y2);
    cudaGetSymbolAddress((void**)&Y3,    g_Y3);
    cudaGetSymbolAddress((void**)&pS,    g_pS);
    cudaGetSymbolAddress((void**)&pS2,   g_pS2);
    cudaGetSymbolAddress((void**)&scale, g_scale);
    cudaGetSymbolAddress((void**)&shift, g_shift);

    // 1) V features: (8192 x 256)
    compute_v_kernel<<<MROWS, 256>>>(x, Q, V);

    // 2) layer 1: Y1 = V @ W1^T + b1 ; BN ; leaky
    gemm_bias_kernel<<<dim3(NH/64, MROWS/64), 256>>>(V, W1, b1, Y1, MROWS, VDIM, NH);
    bn_layer(Y1, g1, bt1, Y1, NH, true, pS, pS2, scale, shift);

    // 3) layer 2
    gemm_bias_kernel<<<dim3(NH/64, MROWS/64), 256>>>(Y1, W2, b2, Y2, MROWS, NH, NH);
    bn_layer(Y2, g2, bt2, Y2, NH, true, pS, pS2, scale, shift);

    // 4) layer 3 (no leaky), BN writes straight to d_out
    gemm_bias_kernel<<<dim3(NO/64, MROWS/64), 256>>>(Y2, W3, b3, Y3, MROWS, NH, NO);
    bn_layer(Y3, g3, bt3, out, NO, false, pS, pS2, scale, shift);
}

// round 3
// speedup vs baseline: 1.8218x; 1.8218x over previous
#include <cuda_runtime.h>
#include <cuda_bf16.h>
#include <cstdint>
#include <math.h>

#define BATCH 16
#define SEQ   512
#define NI    32
#define NHEAD 8
#define NH    512
#define NO    64
#define MROWS (BATCH*SEQ)      // 8192
#define VDIM  (NHEAD*NI)       // 256
#define EPSV  1e-5f
#define SLOPE 0.05f
#define RS    32

// ---------------- scratch ----------------
__device__ float g_V [(size_t)MROWS * VDIM];
__device__ float g_Y1[(size_t)MROWS * NH];
__device__ float g_Y2[(size_t)MROWS * NH];
__device__ float g_Y3[(size_t)MROWS * NO];
__device__ float g_pS [RS * NH];
__device__ float g_pS2[RS * NH];
__device__ float g_scale[NH];
__device__ float g_shift[NH];

// ---------------- kernel 1: V features ----------------
// block: 256 threads = 8 warps; warp w handles n = n0 + w; 8 n per block
__global__ void __launch_bounds__(256) compute_v_kernel(
    const float* __restrict__ x, const float* __restrict__ Q, float* __restrict__ V)
{
    const int bx  = blockIdx.x;
    const int b   = bx >> 6;
    const int n0  = (bx & 63) * 8;
    const int tid = threadIdx.x;
    const int w   = tid >> 5;
    const int i   = tid & 31;

    __shared__ float xs[64][33];
    __shared__ float ws[8][64][8];   // [n_local][m][h]
    __shared__ float qs[8][4];
    __shared__ float pn[8][3];

    const float* xb = x + (size_t)b * SEQ * NI;

    if (tid < 8) {
        float a = Q[tid*3+0], bq = Q[tid*3+1], cq = Q[tid*3+2];
        qs[tid][0] = a; qs[tid][1] = bq; qs[tid][2] = cq;
        qs[tid][3] = a*a + bq*bq + cq*cq;
    }
    if (tid < 24) {
        pn[tid/3][tid%3] = xb[(n0 + tid/3)*NI + (tid%3)];
    }
    __syncthreads();

    float acc[8] = {0.f,0.f,0.f,0.f,0.f,0.f,0.f,0.f};

    for (int m0 = 0; m0 < SEQ; m0 += 64) {
        const float* src = xb + (size_t)m0 * NI;
        #pragma unroll
        for (int idx4 = tid; idx4 < 512; idx4 += 256) {
            float4 v = *(const float4*)(src + idx4*4);
            int r = idx4 >> 3, c = (idx4 & 7) * 4;
            xs[r][c+0] = v.x; xs[r][c+1] = v.y; xs[r][c+2] = v.z; xs[r][c+3] = v.w;
        }
        __syncthreads();

        #pragma unroll
        for (int p = tid; p < 512; p += 256) {
            int nl = p >> 6, mm = p & 63;
            float dx = pn[nl][0] - xs[mm][0];
            float dy = pn[nl][1] - xs[mm][1];
            float dz = pn[nl][2] - xs[mm][2];
            float d2 = dx*dx + dy*dy + dz*dz;
            float e[8];
            #pragma unroll
            for (int h = 0; h < 8; h++) {
                float dq = dx*qs[h][0] + dy*qs[h][1] + dz*qs[h][2];
                e[h] = __expf(2.f*dq - d2 - qs[h][3]);
            }
            float4* wp = (float4*)&ws[nl][mm][0];
            wp[0] = make_float4(e[0], e[1], e[2], e[3]);
            wp[1] = make_float4(e[4], e[5], e[6], e[7]);
        }
        __syncthreads();

        const float* wrow = &ws[w][0][0];
        #pragma unroll 8
        for (int mm = 0; mm < 64; mm++) {
            float xv = xs[mm][i];
            float4 wa = *(const float4*)(wrow + mm*8);
            float4 wb = *(const float4*)(wrow + mm*8 + 4);
            acc[0] = fmaf(wa.x, xv, acc[0]);
            acc[1] = fmaf(wa.y, xv, acc[1]);
            acc[2] = fmaf(wa.z, xv, acc[2]);
            acc[3] = fmaf(wa.w, xv, acc[3]);
            acc[4] = fmaf(wb.x, xv, acc[4]);
            acc[5] = fmaf(wb.y, xv, acc[5]);
            acc[6] = fmaf(wb.z, xv, acc[6]);
            acc[7] = fmaf(wb.w, xv, acc[7]);
        }
        __syncthreads();
    }

    if (i < 3) {
        float p = pn[w][i];
        #pragma unroll
        for (int h = 0; h < 8; h++) acc[h] -= p;
    }
    float* vrow = V + (size_t)(b*SEQ + n0 + w) * VDIM;
    #pragma unroll
    for (int h = 0; h < 8; h++) vrow[h*32 + i] = acc[h];
}

// ================= mma.sync bf16 GEMM (hi/lo split, fp32 accum) =================
__device__ __forceinline__ void mma_bf16(float* d, const uint32_t* a, const uint32_t* b) {
    asm volatile(
        "mma.sync.aligned.m16n8k16.row.col.f32.bf16.bf16.f32 "
        "{%0,%1,%2,%3}, {%4,%5,%6,%7}, {%8,%9}, {%0,%1,%2,%3};"
        : "+f"(d[0]), "+f"(d[1]), "+f"(d[2]), "+f"(d[3])
        : "r"(a[0]), "r"(a[1]), "r"(a[2]), "r"(a[3]), "r"(b[0]), "r"(b[1]));
}

__device__ __forceinline__ void split_pair(float v0, float v1, uint32_t& hi, uint32_t& lo) {
    __nv_bfloat16 h0 = __float2bfloat16(v0);
    __nv_bfloat16 h1 = __float2bfloat16(v1);
    float r0 = v0 - __bfloat162float(h0);
    float r1 = v1 - __bfloat162float(h1);
    __nv_bfloat16 l0 = __float2bfloat16(r0);
    __nv_bfloat16 l1 = __float2bfloat16(r1);
    hi = ((uint32_t)__bfloat16_as_ushort(h1) << 16) | __bfloat16_as_ushort(h0);
    lo = ((uint32_t)__bfloat16_as_ushort(l1) << 16) | __bfloat16_as_ushort(l0);
}

// Y[m][c] = bias[c] + sum_k A'[m][k] * W[c][k];  A' = leaky(BN(A)) if BNA
// Block tile 128 x TN, BK=32, 8 warps (4m x 2n), warp tile 32 x (TN/2)
template<int TN, bool BNA>
__global__ void __launch_bounds__(256) gemm_mma_kernel(
    const float* __restrict__ A, const float* __restrict__ W,
    const float* __restrict__ bias,
    const float* __restrict__ sc, const float* __restrict__ sh,
    float* __restrict__ Y, int M, int K, int C)
{
    constexpr int BK    = 32;
    constexpr int RSU   = BK/2 + 2;        // u32 row stride (18)
    constexpr int NFRAG = TN/16;           // n-tiles of 8 per warp
    constexpr int ALD   = 4;               // float4 per thread for A tile
    constexpr int BLD   = TN/32;           // float4 per thread for B tile

    extern __shared__ uint32_t smem_u[];
    uint32_t* Ahi = smem_u;
    uint32_t* Alo = Ahi + 2*128*RSU;
    uint32_t* Bhi = Alo + 2*128*RSU;
    uint32_t* Blo = Bhi + 2*TN*RSU;

    const int tid  = threadIdx.x;
    const int wid  = tid >> 5, lane = tid & 31;
    const int wm   = (wid >> 1) * 32;
    const int wn   = (wid & 1) * (TN/2);
    const int l4   = lane >> 2, lk = lane & 3;
    const int m0   = blockIdx.y * 128, c0 = blockIdx.x * TN;

    float acc[2][NFRAG][4];
    #pragma unroll
    for (int a = 0; a < 2; a++)
        #pragma unroll
        for (int b = 0; b < NFRAG; b++)
            #pragma unroll
            for (int q = 0; q < 4; q++) acc[a][b][q] = 0.f;

    float4 pa[ALD], pb[BLD];

    auto gload = [&](int t) {
        #pragma unroll
        for (int j = 0; j < ALD; j++) {
            int lin = tid + j*256; int r = lin >> 3; int cc = lin & 7;
            pa[j] = *(const float4*)(A + (size_t)(m0 + r)*K + t*BK + cc*4);
        }
        #pragma unroll
        for (int j = 0; j < BLD; j++) {
            int lin = tid + j*256; int r = lin >> 3; int cc = lin & 7;
            pb[j] = *(const float4*)(W + (size_t)(c0 + r)*K + t*BK + cc*4);
        }
    };

    auto sstore = [&](int t, int buf) {
        #pragma unroll
        for (int j = 0; j < ALD; j++) {
            int lin = tid + j*256; int r = lin >> 3; int cc = lin & 7;
            float v[4] = {pa[j].x, pa[j].y, pa[j].z, pa[j].w};
            if (BNA) {
                int kb = t*BK + cc*4;
                float4 s4 = *(const float4*)(sc + kb);
                float4 h4 = *(const float4*)(sh + kb);
                float scv[4] = {s4.x, s4.y, s4.z, s4.w};
                float shv[4] = {h4.x, h4.y, h4.z, h4.w};
                #pragma unroll
                for (int q = 0; q < 4; q++) {
                    float o = fmaf(scv[q], v[q], shv[q]);
                    v[q] = o > 0.f ? o : o * SLOPE;
                }
            }
            uint32_t hi0, lo0, hi1, lo1;
            split_pair(v[0], v[1], hi0, lo0);
            split_pair(v[2], v[3], hi1, lo1);
            uint32_t off = (uint32_t)(buf*128*RSU + r*RSU + cc*2);
            Ahi[off] = hi0; Ahi[off+1] = hi1;
            Alo[off] = lo0; Alo[off+1] = lo1;
        }
        #pragma unroll
        for (int j = 0; j < BLD; j++) {
            int lin = tid + j*256; int r = lin >> 3; int cc = lin & 7;
            uint32_t hi0, lo0, hi1, lo1;
            split_pair(pb[j].x, pb[j].y, hi0, lo0);
            split_pair(pb[j].z, pb[j].w, hi1, lo1);
            uint32_t off = (uint32_t)(buf*TN*RSU + r*RSU + cc*2);
            Bhi[off] = hi0; Bhi[off+1] = hi1;
            Blo[off] = lo0; Blo[off+1] = lo1;
        }
    };

    auto compute = [&](int buf) {
        const uint32_t* Ah = Ahi + buf*128*RSU;
        const uint32_t* Al = Alo + buf*128*RSU;
        const uint32_t* Bh = Bhi + buf*TN*RSU;
        const uint32_t* Bl = Blo + buf*TN*RSU;
        #pragma unroll
        for (int kk = 0; kk < 2; kk++) {
            uint32_t ah[2][4], al[2][4];
            #pragma unroll
            for (int mi = 0; mi < 2; mi++) {
                int base = (wm + mi*16 + l4)*RSU + kk*8 + lk;
                ah[mi][0] = Ah[base];
                ah[mi][1] = Ah[base + 8*RSU];
                ah[mi][2] = Ah[base + 4];
                ah[mi][3] = Ah[base + 8*RSU + 4];
                al[mi][0] = Al[base];
                al[mi][1] = Al[base + 8*RSU];
                al[mi][2] = Al[base + 4];
                al[mi][3] = Al[base + 8*RSU + 4];
            }
            #pragma unroll
            for (int ni = 0; ni < NFRAG; ni++) {
                int bbase = (wn + ni*8 + l4)*RSU + kk*8 + lk;
                uint32_t bh[2] = {Bh[bbase], Bh[bbase + 4]};
                uint32_t bl[2] = {Bl[bbase], Bl[bbase + 4]};
                #pragma unroll
                for (int mi = 0; mi < 2; mi++) {
                    mma_bf16(acc[mi][ni], ah[mi], bh);
                    mma_bf16(acc[mi][ni], ah[mi], bl);
                    mma_bf16(acc[mi][ni], al[mi], bh);
                }
            }
        }
    };

    const int T = K / BK;
    gload(0);
    for (int t = 0; t < T; t++) {
        int buf = t & 1;
        sstore(t, buf);
        __syncthreads();
        if (t + 1 < T) gload(t + 1);
        compute(buf);
    }

    // epilogue: direct register stores with bias
    #pragma unroll
    for (int mi = 0; mi < 2; mi++) {
        #pragma unroll
        for (int ni = 0; ni < NFRAG; ni++) {
            int row = m0 + wm + mi*16 + l4;
            int col = c0 + wn + ni*8 + lk*2;
            float2 b2 = *(const float2*)(bias + col);
            float2 o0 = make_float2(acc[mi][ni][0] + b2.x, acc[mi][ni][1] + b2.y);
            float2 o1 = make_float2(acc[mi][ni][2] + b2.x, acc[mi][ni][3] + b2.y);
            *(float2*)(Y + (size_t)row * C + col)       = o0;
            *(float2*)(Y + (size_t)(row + 8) * C + col) = o1;
        }
    }
}

// ---------------- stats: partial column sums ----------------
__global__ void __launch_bounds__(256) stats_partial_kernel(
    const float* __restrict__ Y, int M, int C, float* __restrict__ pS, float* __restrict__ pS2)
{
    const int tx = threadIdx.x & 31, ty = threadIdx.x >> 5;
    const int c = blockIdx.x * 32 + tx;
    const int rows = M / RS;
    const int rbeg = blockIdx.y * rows;

    float s = 0.f, s2 = 0.f;
    for (int r = rbeg + ty; r < rbeg + rows; r += 8) {
        float v = Y[(size_t)r * C + c];
        s += v; s2 = fmaf(v, v, s2);
    }
    __shared__ float ss[8][33], ss2[8][33];
    ss[ty][tx] = s; ss2[ty][tx] = s2;
    __syncthreads();
    if (ty == 0) {
        #pragma unroll
        for (int j = 1; j < 8; j++) { s += ss[j][tx]; s2 += ss2[j][tx]; }
        pS [blockIdx.y * C + c] = s;
        pS2[blockIdx.y * C + c] = s2;
    }
}

__global__ void stats_final_kernel(
    const float* __restrict__ pS, const float* __restrict__ pS2,
    const float* __restrict__ g, const float* __restrict__ bt,
    int M, int C, float* __restrict__ scale, float* __restrict__ shift)
{
    const int c = blockIdx.x;
    const int j = threadIdx.x;
    float s  = pS [j * C + c];
    float s2 = pS2[j * C + c];
    #pragma unroll
    for (int off = 16; off > 0; off >>= 1) {
        s  += __shfl_down_sync(0xffffffffu, s,  off);
        s2 += __shfl_down_sync(0xffffffffu, s2, off);
    }
    if (j == 0) {
        float invM = 1.f / (float)M;
        float mean = s * invM;
        float var  = fmaf(-mean, mean, s2 * invM);
        float inv  = rsqrtf(var + EPSV);
        float scv  = g[c] * inv;
        scale[c] = scv;
        shift[c] = fmaf(-mean, scv, bt[c]);
    }
}

// ---------------- final BN apply ----------------
__global__ void __launch_bounds__(256) bnapply_kernel(
    const float* __restrict__ Y, const float* __restrict__ scale,
    const float* __restrict__ shift, float* __restrict__ out, int total4, int C4)
{
    int idx = blockIdx.x * blockDim.x + threadIdx.x;
    if (idx >= total4) return;
    int c4 = idx % C4;
    float4 y  = ((const float4*)Y)[idx];
    float4 sc = ((const float4*)scale)[c4];
    float4 sh = ((const float4*)shift)[c4];
    float4 o;
    o.x = fmaf(y.x, sc.x, sh.x);
    o.y = fmaf(y.y, sc.y, sh.y);
    o.z = fmaf(y.z, sc.z, sh.z);
    o.w = fmaf(y.w, sc.w, sh.w);
    ((float4*)out)[idx] = o;
}

// ---------------- host ----------------
extern "C" void kernel_launch(void* const* d_in, const int* in_sizes, int n_in,
                              void* d_out, int out_size)
{
    const float* x   = (const float*)d_in[0];
    const float* Q   = (const float*)d_in[1];
    const float* W1  = (const float*)d_in[2];
    const float* b1  = (const float*)d_in[3];
    const float* g1  = (const float*)d_in[4];
    const float* bt1 = (const float*)d_in[5];
    const float* W2  = (const float*)d_in[6];
    const float* b2  = (const float*)d_in[7];
    const float* g2  = (const float*)d_in[8];
    const float* bt2 = (const float*)d_in[9];
    const float* W3  = (const float*)d_in[10];
    const float* b3  = (const float*)d_in[11];
    const float* g3  = (const float*)d_in[12];
    const float* bt3 = (const float*)d_in[13];
    float* out = (float*)d_out;

    float *V, *Y1, *Y2, *Y3, *pS, *pS2, *scale, *shift;
    cudaGetSymbolAddress((void**)&V,     g_V);
    cudaGetSymbolAddress((void**)&Y1,    g_Y1);
    cudaGetSymbolAddress((void**)&Y2,    g_Y2);
    cudaGetSymbolAddress((void**)&Y3,    g_Y3);
    cudaGetSymbolAddress((void**)&pS,    g_pS);
    cudaGetSymbolAddress((void**)&pS2,   g_pS2);
    cudaGetSymbolAddress((void**)&scale, g_scale);
    cudaGetSymbolAddress((void**)&shift, g_shift);

    constexpr int RSU = 32/2 + 2;
    const int SMEM128 = RSU * 4 * (128 + 128) * 4;   // 73728 B
    const int SMEM64  = RSU * 4 * (128 + 64)  * 4;   // 55296 B
    cudaFuncSetAttribute(gemm_mma_kernel<128,false>, cudaFuncAttributeMaxDynamicSharedMemorySize, SMEM128);
    cudaFuncSetAttribute(gemm_mma_kernel<128,true >, cudaFuncAttributeMaxDynamicSharedMemorySize, SMEM128);
    cudaFuncSetAttribute(gemm_mma_kernel<64, true >, cudaFuncAttributeMaxDynamicSharedMemorySize, SMEM64);

    // 1) V features
    compute_v_kernel<<<MROWS/8, 256>>>(x, Q, V);

    // 2) layer 1: Y1 = V @ W1^T + b1; stats
    gemm_mma_kernel<128,false><<<dim3(NH/128, MROWS/128), 256, SMEM128>>>(
        V, W1, b1, nullptr, nullptr, Y1, MROWS, VDIM, NH);
    stats_partial_kernel<<<dim3(NH/32, RS), 256>>>(Y1, MROWS, NH, pS, pS2);
    stats_final_kernel<<<NH, 32>>>(pS, pS2, g1, bt1, MROWS, NH, scale, shift);

    // 3) layer 2: BN1+leaky fused into A-load
    gemm_mma_kernel<128,true><<<dim3(NH/128, MROWS/128), 256, SMEM128>>>(
        Y1, W2, b2, scale, shift, Y2, MROWS, NH, NH);
    stats_partial_kernel<<<dim3(NH/32, RS), 256>>>(Y2, MROWS, NH, pS, pS2);
    stats_final_kernel<<<NH, 32>>>(pS, pS2, g2, bt2, MROWS, NH, scale, shift);

    // 4) layer 3: BN2+leaky fused into A-load
    gemm_mma_kernel<64,true><<<dim3(NO/64, MROWS/128), 256, SMEM64>>>(
        Y2, W3, b3, scale, shift, Y3, MROWS, NH, NO);
    stats_partial_kernel<<<dim3(NO/32, RS), 256>>>(Y3, MROWS, NO, pS, pS2);
    stats_final_kernel<<<NO, 32>>>(pS, pS2, g3, bt3, MROWS, NO, scale, shift);

    // 5) final BN apply -> out
    int total4 = MROWS * NO / 4;
    bnapply_kernel<<<(total4 + 255)/256, 256>>>(Y3, scale, shift, out, total4, NO/4);
}

// round 5
// speedup vs baseline: 2.4045x; 1.3199x over previous
#include <cuda_runtime.h>
#include <cuda_bf16.h>
#include <cstdint>
#include <math.h>

#define BATCH 16
#define SEQ   512
#define NI    32
#define NHEAD 8
#define NH    512
#define NO    64
#define MROWS (BATCH*SEQ)      // 8192
#define VDIM  (NHEAD*NI)       // 256
#define EPSV  1e-5f
#define SLOPE 0.05f
#define RS    32

// ---------------- scratch ----------------
__device__ float    g_En  [16*8*512];
__device__ uint32_t g_Xthi[(size_t)16*256*256], g_Xtlo[(size_t)16*256*256];
__device__ uint32_t g_Ghi [(size_t)16*512*256], g_Glo [(size_t)16*512*256];
__device__ uint32_t g_Vhi [(size_t)8192*128],   g_Vlo [(size_t)8192*128];
__device__ uint32_t g_W1hi[512*128], g_W1lo[512*128];
__device__ uint32_t g_W2hi[512*256], g_W2lo[512*256];
__device__ uint32_t g_W3hi[64*256],  g_W3lo[64*256];
__device__ uint32_t g_Axhi[(size_t)8192*256],   g_Axlo[(size_t)8192*256];
__device__ float g_Y1[(size_t)MROWS * NH];
__device__ float g_Y2[(size_t)MROWS * NH];
__device__ float g_Y3[(size_t)MROWS * NO];
__device__ float g_pS [RS * NH];
__device__ float g_pS2[RS * NH];
__device__ float g_scale[NH];
__device__ float g_shift[NH];

// ---------------- helpers ----------------
__device__ __forceinline__ void split_pair(float v0, float v1, uint32_t& hi, uint32_t& lo) {
    __nv_bfloat16 h0 = __float2bfloat16(v0);
    __nv_bfloat16 h1 = __float2bfloat16(v1);
    float r0 = v0 - __bfloat162float(h0);
    float r1 = v1 - __bfloat162float(h1);
    __nv_bfloat16 l0 = __float2bfloat16(r0);
    __nv_bfloat16 l1 = __float2bfloat16(r1);
    hi = ((uint32_t)__bfloat16_as_ushort(h1) << 16) | __bfloat16_as_ushort(h0);
    lo = ((uint32_t)__bfloat16_as_ushort(l1) << 16) | __bfloat16_as_ushort(l0);
}

__device__ __forceinline__ void mma_bf16(float* d, const uint32_t* a, const uint32_t* b) {
    asm volatile(
        "mma.sync.aligned.m16n8k16.row.col.f32.bf16.bf16.f32 "
        "{%0,%1,%2,%3}, {%4,%5,%6,%7}, {%8,%9}, {%0,%1,%2,%3};"
        : "+f"(d[0]), "+f"(d[1]), "+f"(d[2]), "+f"(d[3])
        : "r"(a[0]), "r"(a[1]), "r"(a[2]), "r"(a[3]), "r"(b[0]), "r"(b[1]));
}

// ---------------- prep: En tables, Xt build, W split ----------------
__global__ void __launch_bounds__(256) prep_kernel(
    const float* __restrict__ x, const float* __restrict__ Q,
    float* __restrict__ En,
    uint32_t* __restrict__ Xthi, uint32_t* __restrict__ Xtlo,
    const float* __restrict__ W1, uint32_t* __restrict__ W1hi, uint32_t* __restrict__ W1lo,
    const float* __restrict__ W2, uint32_t* __restrict__ W2hi, uint32_t* __restrict__ W2lo,
    const float* __restrict__ W3, uint32_t* __restrict__ W3hi, uint32_t* __restrict__ W3lo)
{
    const int blk = blockIdx.x;
    const int tid = threadIdx.x;

    if (blk >= 64) {
        int widx = blk - 64;
        const float* src; uint32_t* hi; uint32_t* lo; int base;
        if (widx < 32)      { src = W1; hi = W1hi; lo = W1lo; base = widx * 2048; }
        else if (widx < 96) { src = W2; hi = W2hi; lo = W2lo; base = (widx - 32) * 2048; }
        else                { src = W3; hi = W3hi; lo = W3lo; base = (widx - 96) * 2048; }
        int p = base + tid;
        #pragma unroll
        for (int j = 0; j < 8; j++, p += 256) {
            float2 v = ((const float2*)src)[p];
            uint32_t h, l; split_pair(v.x, v.y, h, l);
            hi[p] = h; lo[p] = l;
        }
        return;
    }

    const int b = blk >> 2, chunk = blk & 3;   // 128 m per chunk

    __shared__ float sEm[8][128];
    __shared__ float sQ[8][4];
    __shared__ uint32_t shi[256][8], slo[256][8];

    if (tid < 8) {
        float a = Q[tid*3+0], bq = Q[tid*3+1], cq = Q[tid*3+2];
        sQ[tid][0] = a; sQ[tid][1] = bq; sQ[tid][2] = cq;
        sQ[tid][3] = a*a + bq*bq + cq*cq;
    }
    __syncthreads();

    if (tid < 128) {
        int m = chunk*128 + tid;
        const float* xp = x + ((size_t)b*512 + m)*32;
        float px = xp[0], py = xp[1], pz = xp[2];
        #pragma unroll
        for (int h = 0; h < 8; h++) {
            float dot = px*sQ[h][0] + py*sQ[h][1] + pz*sQ[h][2];
            float em = __expf(-2.f*dot);
            float en = __expf(2.f*dot - sQ[h][3]);
            sEm[h][tid] = em;
            En[((size_t)b*8 + h)*512 + m] = en;
        }
    }
    __syncthreads();

    const int c = tid, h = c >> 5, i = c & 31;
    for (int grp = 0; grp < 8; grp++) {
        #pragma unroll
        for (int j = 0; j < 8; j++) {
            int mloc = (grp*8 + j)*2;
            int m = chunk*128 + mloc;
            float v0 = sEm[h][mloc]   * x[((size_t)b*512 + m  )*32 + i];
            float v1 = sEm[h][mloc+1] * x[((size_t)b*512 + m+1)*32 + i];
            uint32_t hh, ll; split_pair(v0, v1, hh, ll);
            shi[c][j] = hh; slo[c][j] = ll;
        }
        __syncthreads();
        int cc = tid >> 3, j2 = tid & 7;
        #pragma unroll
        for (int rep = 0; rep < 8; rep++) {
            int ccc = cc + rep*32;
            size_t addr = ((size_t)b*256 + ccc)*256 + chunk*64 + grp*8 + j2;
            Xthi[addr] = shi[ccc][j2];
            Xtlo[addr] = slo[ccc][j2];
        }
        __syncthreads();
    }
}

// ---------------- buildG ----------------
__global__ void __launch_bounds__(256) buildG_kernel(
    const float* __restrict__ x, uint32_t* __restrict__ Ghi, uint32_t* __restrict__ Glo)
{
    const int b  = blockIdx.x >> 3, nt = blockIdx.x & 7;
    const int tid = threadIdx.x;
    const int n = tid & 63, mq = tid >> 6;

    __shared__ float pn3[64][5];
    __shared__ float pm3[128][4];

    if (tid < 64) {
        const float* xp = x + ((size_t)b*512 + nt*64 + tid)*32;
        pn3[tid][0] = xp[0]; pn3[tid][1] = xp[1]; pn3[tid][2] = xp[2];
    }

    for (int mc = 0; mc < 4; mc++) {
        __syncthreads();
        if (tid < 128) {
            const float* xp = x + ((size_t)b*512 + mc*128 + tid)*32;
            pm3[tid][0] = xp[0]; pm3[tid][1] = xp[1]; pm3[tid][2] = xp[2];
        }
        __syncthreads();
        float px = pn3[n][0], py = pn3[n][1], pz = pn3[n][2];
        uint32_t outh[16], outl[16];
        #pragma unroll
        for (int j = 0; j < 16; j++) {
            int ml = mq*32 + j*2;
            float dx0 = px - pm3[ml][0],   dy0 = py - pm3[ml][1],   dz0 = pz - pm3[ml][2];
            float dx1 = px - pm3[ml+1][0], dy1 = py - pm3[ml+1][1], dz1 = pz - pm3[ml+1][2];
            float e0 = __expf(-(dx0*dx0 + dy0*dy0 + dz0*dz0));
            float e1 = __expf(-(dx1*dx1 + dy1*dy1 + dz1*dz1));
            split_pair(e0, e1, outh[j], outl[j]);
        }
        size_t base = ((size_t)b*512 + nt*64 + n)*256 + mc*64 + mq*16;
        #pragma unroll
        for (int j4 = 0; j4 < 4; j4++) {
            ((uint4*)(Ghi + base))[j4] = make_uint4(outh[j4*4], outh[j4*4+1], outh[j4*4+2], outh[j4*4+3]);
            ((uint4*)(Glo + base))[j4] = make_uint4(outl[j4*4], outl[j4*4+1], outl[j4*4+2], outl[j4*4+3]);
        }
    }
}

// ================= shared GEMM machinery =================
#define RSU 20

// ---------------- vgemm: V = En .* (G @ Xt^T) - pos ----------------
__global__ void __launch_bounds__(256) vgemm_kernel(
    const uint32_t* __restrict__ Ghi, const uint32_t* __restrict__ Glo,
    const uint32_t* __restrict__ Bhi_g, const uint32_t* __restrict__ Blo_g,
    const float* __restrict__ En, const float* __restrict__ x,
    uint32_t* __restrict__ Vhi, uint32_t* __restrict__ Vlo)
{
    constexpr int TN = 128, NFRAG = TN/16, KE = 512, K2 = KE/2;
    extern __shared__ uint32_t smem_u[];
    uint32_t* Ahs = smem_u;
    uint32_t* Als = Ahs + 2*128*RSU;
    uint32_t* Bhs = Als + 2*128*RSU;
    uint32_t* Bls = Bhs + 2*TN*RSU;

    const int tid = threadIdx.x, wid = tid >> 5, lane = tid & 31;
    const int wm = (wid >> 1) * 32, wn = (wid & 1) * (TN/2);
    const int l4 = lane >> 2, lk = lane & 3;
    const int b = blockIdx.z;
    const int m0 = blockIdx.y * 128, c0 = blockIdx.x * TN;

    const uint32_t* Ah_g = Ghi + (size_t)b*512*K2;
    const uint32_t* Al_g = Glo + (size_t)b*512*K2;
    const uint32_t* Bh_g = Bhi_g + (size_t)b*256*K2;
    const uint32_t* Bl_g = Blo_g + (size_t)b*256*K2;

    float acc[2][NFRAG][4];
    #pragma unroll
    for (int a = 0; a < 2; a++)
        #pragma unroll
        for (int q = 0; q < NFRAG; q++)
            { acc[a][q][0]=0.f; acc[a][q][1]=0.f; acc[a][q][2]=0.f; acc[a][q][3]=0.f; }

    uint4 pah[2], pal[2], pbh[2], pbl[2];
    auto gload = [&](int t) {
        #pragma unroll
        for (int j = 0; j < 2; j++) {
            int lin = tid + j*256; int r = lin >> 2, q = lin & 3;
            size_t ao = (size_t)(m0 + r)*K2 + t*16 + q*4;
            pah[j] = *(const uint4*)(Ah_g + ao);
            pal[j] = *(const uint4*)(Al_g + ao);
            size_t bo = (size_t)(c0 + r)*K2 + t*16 + q*4;
            pbh[j] = *(const uint4*)(Bh_g + bo);
            pbl[j] = *(const uint4*)(Bl_g + bo);
        }
    };
    auto sstore = [&](int buf) {
        #pragma unroll
        for (int j = 0; j < 2; j++) {
            int lin = tid + j*256; int r = lin >> 2, q = lin & 3;
            uint32_t off = (uint32_t)(buf*128*RSU + r*RSU + q*4);
            *(uint4*)(Ahs + off) = pah[j];
            *(uint4*)(Als + off) = pal[j];
            uint32_t offb = (uint32_t)(buf*TN*RSU + r*RSU + q*4);
            *(uint4*)(Bhs + offb) = pbh[j];
            *(uint4*)(Bls + offb) = pbl[j];
        }
    };
    auto compute = [&](int buf) {
        const uint32_t* Ah = Ahs + buf*128*RSU;
        const uint32_t* Al = Als + buf*128*RSU;
        const uint32_t* Bh = Bhs + buf*TN*RSU;
        const uint32_t* Bl = Bls + buf*TN*RSU;
        #pragma unroll
        for (int kk = 0; kk < 2; kk++) {
            uint32_t ah[2][4], al[2][4];
            #pragma unroll
            for (int mi = 0; mi < 2; mi++) {
                int base = (wm + mi*16 + l4)*RSU + kk*8 + lk;
                ah[mi][0] = Ah[base];        ah[mi][1] = Ah[base + 8*RSU];
                ah[mi][2] = Ah[base + 4];    ah[mi][3] = Ah[base + 8*RSU + 4];
                al[mi][0] = Al[base];        al[mi][1] = Al[base + 8*RSU];
                al[mi][2] = Al[base + 4];    al[mi][3] = Al[base + 8*RSU + 4];
            }
            #pragma unroll
            for (int ni = 0; ni < NFRAG; ni++) {
                int bbase = (wn + ni*8 + l4)*RSU + kk*8 + lk;
                uint32_t bh[2] = {Bh[bbase], Bh[bbase + 4]};
                uint32_t bl[2] = {Bl[bbase], Bl[bbase + 4]};
                #pragma unroll
                for (int mi = 0; mi < 2; mi++) {
                    mma_bf16(acc[mi][ni], ah[mi], bh);
                    mma_bf16(acc[mi][ni], ah[mi], bl);
                    mma_bf16(acc[mi][ni], al[mi], bh);
                }
            }
        }
    };

    const int T = KE / 32;
    gload(0);
    for (int t = 0; t < T; t++) {
        int buf = t & 1;
        sstore(buf);
        __syncthreads();
        if (t + 1 < T) gload(t + 1);
        compute(buf);
        __syncthreads();
    }

    // epilogue: scale by En, subtract pos for i<3, split to bf16
    #pragma unroll
    for (int mi = 0; mi < 2; mi++) {
        #pragma unroll
        for (int ni = 0; ni < NFRAG; ni++) {
            int n0 = m0 + wm + mi*16 + l4;
            int cc = c0 + wn + ni*8 + lk*2;     // FIXED: include block column offset
            int h = cc >> 5, il = cc & 31;
            float en0 = En[((size_t)b*8 + h)*512 + n0];
            float en1 = En[((size_t)b*8 + h)*512 + n0 + 8];
            float v00 = acc[mi][ni][0]*en0, v01 = acc[mi][ni][1]*en0;
            float v10 = acc[mi][ni][2]*en1, v11 = acc[mi][ni][3]*en1;
            if (il < 3) {
                v00 -= x[((size_t)b*512 + n0  )*32 + il];
                v10 -= x[((size_t)b*512 + n0+8)*32 + il];
            }
            if (il + 1 < 3) {
                v01 -= x[((size_t)b*512 + n0  )*32 + il + 1];
                v11 -= x[((size_t)b*512 + n0+8)*32 + il + 1];
            }
            uint32_t h0, l0, h1, l1;
            split_pair(v00, v01, h0, l0);
            split_pair(v10, v11, h1, l1);
            size_t r0 = ((size_t)b*512 + n0)*128 + (cc >> 1);
            size_t r1 = ((size_t)b*512 + n0 + 8)*128 + (cc >> 1);
            Vhi[r0] = h0; Vlo[r0] = l0;
            Vhi[r1] = h1; Vlo[r1] = l1;
        }
    }
}

// ---------------- gemm_ps ----------------
template<int TN>
__global__ void __launch_bounds__(256) gemm_ps_kernel(
    const uint32_t* __restrict__ Ah_g, const uint32_t* __restrict__ Al_g,
    const uint32_t* __restrict__ Bh_g, const uint32_t* __restrict__ Bl_g,
    const float* __restrict__ bias, float* __restrict__ Y, int K, int C)
{
    constexpr int NFRAG = TN/16;
    constexpr int BLD4 = TN/64;
    extern __shared__ uint32_t smem_u[];
    uint32_t* Ahs = smem_u;
    uint32_t* Als = Ahs + 2*128*RSU;
    uint32_t* Bhs = Als + 2*128*RSU;
    uint32_t* Bls = Bhs + 2*TN*RSU;

    const int tid = threadIdx.x, wid = tid >> 5, lane = tid & 31;
    const int wm = (wid >> 1) * 32, wn = (wid & 1) * (TN/2);
    const int l4 = lane >> 2, lk = lane & 3;
    const int m0 = blockIdx.y * 128, c0 = blockIdx.x * TN;
    const int K2 = K >> 1;

    float acc[2][NFRAG][4];
    #pragma unroll
    for (int a = 0; a < 2; a++)
        #pragma unroll
        for (int q = 0; q < NFRAG; q++)
            { acc[a][q][0]=0.f; acc[a][q][1]=0.f; acc[a][q][2]=0.f; acc[a][q][3]=0.f; }

    uint4 pah[2], pal[2], pbh[BLD4], pbl[BLD4];
    auto gload = [&](int t) {
        #pragma unroll
        for (int j = 0; j < 2; j++) {
            int lin = tid + j*256; int r = lin >> 2, q = lin & 3;
            size_t ao = (size_t)(m0 + r)*K2 + t*16 + q*4;
            pah[j] = *(const uint4*)(Ah_g + ao);
            pal[j] = *(const uint4*)(Al_g + ao);
        }
        #pragma unroll
        for (int j = 0; j < BLD4; j++) {
            int lin = tid + j*256; int r = lin >> 2, q = lin & 3;
            size_t bo = (size_t)(c0 + r)*K2 + t*16 + q*4;
            pbh[j] = *(const uint4*)(Bh_g + bo);
            pbl[j] = *(const uint4*)(Bl_g + bo);
        }
    };
    auto sstore = [&](int buf) {
        #pragma unroll
        for (int j = 0; j < 2; j++) {
            int lin = tid + j*256; int r = lin >> 2, q = lin & 3;
            uint32_t off = (uint32_t)(buf*128*RSU + r*RSU + q*4);
            *(uint4*)(Ahs + off) = pah[j];
            *(uint4*)(Als + off) = pal[j];
        }
        #pragma unroll
        for (int j = 0; j < BLD4; j++) {
            int lin = tid + j*256; int r = lin >> 2, q = lin & 3;
            uint32_t off = (uint32_t)(buf*TN*RSU + r*RSU + q*4);
            *(uint4*)(Bhs + off) = pbh[j];
            *(uint4*)(Bls + off) = pbl[j];
        }
    };
    auto compute = [&](int buf) {
        const uint32_t* Ah = Ahs + buf*128*RSU;
        const uint32_t* Al = Als + buf*128*RSU;
        const uint32_t* Bh = Bhs + buf*TN*RSU;
        const uint32_t* Bl = Bls + buf*TN*RSU;
        #pragma unroll
        for (int kk = 0; kk < 2; kk++) {
            uint32_t ah[2][4], al[2][4];
            #pragma unroll
            for (int mi = 0; mi < 2; mi++) {
                int base = (wm + mi*16 + l4)*RSU + kk*8 + lk;
                ah[mi][0] = Ah[base];        ah[mi][1] = Ah[base + 8*RSU];
                ah[mi][2] = Ah[base + 4];    ah[mi][3] = Ah[base + 8*RSU + 4];
                al[mi][0] = Al[base];        al[mi][1] = Al[base + 8*RSU];
                al[mi][2] = Al[base + 4];    al[mi][3] = Al[base + 8*RSU + 4];
            }
            #pragma unroll
            for (int ni = 0; ni < NFRAG; ni++) {
                int bbase = (wn + ni*8 + l4)*RSU + kk*8 + lk;
                uint32_t bh[2] = {Bh[bbase], Bh[bbase + 4]};
                uint32_t bl[2] = {Bl[bbase], Bl[bbase + 4]};
                #pragma unroll
                for (int mi = 0; mi < 2; mi++) {
                    mma_bf16(acc[mi][ni], ah[mi], bh);
                    mma_bf16(acc[mi][ni], ah[mi], bl);
                    mma_bf16(acc[mi][ni], al[mi], bh);
                }
            }
        }
    };

    const int T = K / 32;
    gload(0);
    for (int t = 0; t < T; t++) {
        int buf = t & 1;
        sstore(buf);
        __syncthreads();
        if (t + 1 < T) gload(t + 1);
        compute(buf);
        __syncthreads();
    }

    #pragma unroll
    for (int mi = 0; mi < 2; mi++) {
        #pragma unroll
        for (int ni = 0; ni < NFRAG; ni++) {
            int row = m0 + wm + mi*16 + l4;
            int col = c0 + wn + ni*8 + lk*2;
            float2 b2 = *(const float2*)(bias + col);
            float2 o0 = make_float2(acc[mi][ni][0] + b2.x, acc[mi][ni][1] + b2.y);
            float2 o1 = make_float2(acc[mi][ni][2] + b2.x, acc[mi][ni][3] + b2.y);
            *(float2*)(Y + (size_t)row * C + col)       = o0;
            *(float2*)(Y + (size_t)(row + 8) * C + col) = o1;
        }
    }
}

// ---------------- stats ----------------
__global__ void __launch_bounds__(256) stats_partial_kernel(
    const float* __restrict__ Y, int M, int C, float* __restrict__ pS, float* __restrict__ pS2)
{
    const int tx = threadIdx.x & 31, ty = threadIdx.x >> 5;
    const int c = blockIdx.x * 32 + tx;
    const int rows = M / RS;
    const int rbeg = blockIdx.y * rows;

    float s = 0.f, s2 = 0.f;
    for (int r = rbeg + ty; r < rbeg + rows; r += 8) {
        float v = Y[(size_t)r * C + c];
        s += v; s2 = fmaf(v, v, s2);
    }
    __shared__ float ss[8][33], ss2[8][33];
    ss[ty][tx] = s; ss2[ty][tx] = s2;
    __syncthreads();
    if (ty == 0) {
        #pragma unroll
        for (int j = 1; j < 8; j++) { s += ss[j][tx]; s2 += ss2[j][tx]; }
        pS [blockIdx.y * C + c] = s;
        pS2[blockIdx.y * C + c] = s2;
    }
}

__global__ void __launch_bounds__(256) stats_final_kernel(
    const float* __restrict__ pS, const float* __restrict__ pS2,
    const float* __restrict__ g, const float* __restrict__ bt,
    int M, int C, float* __restrict__ scale, float* __restrict__ shift)
{
    const int c = blockIdx.x * 8 + (threadIdx.x >> 5);
    const int j = threadIdx.x & 31;
    float s  = pS [j * C + c];
    float s2 = pS2[j * C + c];
    #pragma unroll
    for (int off = 16; off > 0; off >>= 1) {
        s  += __shfl_down_sync(0xffffffffu, s,  off);
        s2 += __shfl_down_sync(0xffffffffu, s2, off);
    }
    if (j == 0) {
        float invM = 1.f / (float)M;
        float mean = s * invM;
        float var  = fmaf(-mean, mean, s2 * invM);
        float inv  = rsqrtf(var + EPSV);
        float scv  = g[c] * inv;
        scale[c] = scv;
        shift[c] = fmaf(-mean, scv, bt[c]);
    }
}

// ---------------- bnconvert ----------------
__global__ void __launch_bounds__(256) bnconvert_kernel(
    const float* __restrict__ Y, const float* __restrict__ scale,
    const float* __restrict__ shift, uint32_t* __restrict__ hi, uint32_t* __restrict__ lo,
    int total4, int C4)
{
    int idx = blockIdx.x * blockDim.x + threadIdx.x;
    if (idx >= total4) return;
    int c4 = idx % C4;
    float4 y  = ((const float4*)Y)[idx];
    float4 sc = ((const float4*)scale)[c4];
    float4 sh = ((const float4*)shift)[c4];
    float v[4];
    v[0] = fmaf(y.x, sc.x, sh.x); v[1] = fmaf(y.y, sc.y, sh.y);
    v[2] = fmaf(y.z, sc.z, sh.z); v[3] = fmaf(y.w, sc.w, sh.w);
    #pragma unroll
    for (int q = 0; q < 4; q++) v[q] = v[q] > 0.f ? v[q] : v[q] * SLOPE;
    uint32_t h0, l0, h1, l1;
    split_pair(v[0], v[1], h0, l0);
    split_pair(v[2], v[3], h1, l1);
    ((uint2*)hi)[idx] = make_uint2(h0, h1);
    ((uint2*)lo)[idx] = make_uint2(l0, l1);
}

// ---------------- final BN apply ----------------
__global__ void __launch_bounds__(256) bnapply_kernel(
    const float* __restrict__ Y, const float* __restrict__ scale,
    const float* __restrict__ shift, float* __restrict__ out, int total4, int C4)
{
    int idx = blockIdx.x * blockDim.x + threadIdx.x;
    if (idx >= total4) return;
    int c4 = idx % C4;
    float4 y  = ((const float4*)Y)[idx];
    float4 sc = ((const float4*)scale)[c4];
    float4 sh = ((const float4*)shift)[c4];
    float4 o;
    o.x = fmaf(y.x, sc.x, sh.x);
    o.y = fmaf(y.y, sc.y, sh.y);
    o.z = fmaf(y.z, sc.z, sh.z);
    o.w = fmaf(y.w, sc.w, sh.w);
    ((float4*)out)[idx] = o;
}

// ---------------- host ----------------
extern "C" void kernel_launch(void* const* d_in, const int* in_sizes, int n_in,
                              void* d_out, int out_size)
{
    const float* x   = (const float*)d_in[0];
    const float* Q   = (const float*)d_in[1];
    const float* W1  = (const float*)d_in[2];
    const float* b1  = (const float*)d_in[3];
    const float* g1  = (const float*)d_in[4];
    const float* bt1 = (const float*)d_in[5];
    const float* W2  = (const float*)d_in[6];
    const float* b2  = (const float*)d_in[7];
    const float* g2  = (const float*)d_in[8];
    const float* bt2 = (const float*)d_in[9];
    const float* W3  = (const float*)d_in[10];
    const float* b3  = (const float*)d_in[11];
    const float* g3  = (const float*)d_in[12];
    const float* bt3 = (const float*)d_in[13];
    float* out = (float*)d_out;

    float *En, *Y1, *Y2, *Y3, *pS, *pS2, *scale, *shift;
    uint32_t *Xthi, *Xtlo, *Ghi, *Glo, *Vhi, *Vlo, *Axhi, *Axlo;
    uint32_t *W1hi, *W1lo, *W2hi, *W2lo, *W3hi, *W3lo;
    cudaGetSymbolAddress((void**)&En,   g_En);
    cudaGetSymbolAddress((void**)&Xthi, g_Xthi);  cudaGetSymbolAddress((void**)&Xtlo, g_Xtlo);
    cudaGetSymbolAddress((void**)&Ghi,  g_Ghi);   cudaGetSymbolAddress((void**)&Glo,  g_Glo);
    cudaGetSymbolAddress((void**)&Vhi,  g_Vhi);   cudaGetSymbolAddress((void**)&Vlo,  g_Vlo);
    cudaGetSymbolAddress((void**)&Axhi, g_Axhi);  cudaGetSymbolAddress((void**)&Axlo, g_Axlo);
    cudaGetSymbolAddress((void**)&W1hi, g_W1hi);  cudaGetSymbolAddress((void**)&W1lo, g_W1lo);
    cudaGetSymbolAddress((void**)&W2hi, g_W2hi);  cudaGetSymbolAddress((void**)&W2lo, g_W2lo);
    cudaGetSymbolAddress((void**)&W3hi, g_W3hi);  cudaGetSymbolAddress((void**)&W3lo, g_W3lo);
    cudaGetSymbolAddress((void**)&Y1, g_Y1);
    cudaGetSymbolAddress((void**)&Y2, g_Y2);
    cudaGetSymbolAddress((void**)&Y3, g_Y3);
    cudaGetSymbolAddress((void**)&pS, g_pS);      cudaGetSymbolAddress((void**)&pS2, g_pS2);
    cudaGetSymbolAddress((void**)&scale, g_scale); cudaGetSymbolAddress((void**)&shift, g_shift);

    const int SMEM128 = RSU * (2*128 + 2*128) * 2 * 4;   // 81920 B
    const int SMEM64  = RSU * (2*128 + 2*64)  * 2 * 4;   // 61440 B
    cudaFuncSetAttribute(vgemm_kernel,       cudaFuncAttributeMaxDynamicSharedMemorySize, SMEM128);
    cudaFuncSetAttribute(gemm_ps_kernel<128>, cudaFuncAttributeMaxDynamicSharedMemorySize, SMEM128);
    cudaFuncSetAttribute(gemm_ps_kernel<64>,  cudaFuncAttributeMaxDynamicSharedMemorySize, SMEM64);

    // 1) prep: En/Xt + W splits ; buildG
    prep_kernel<<<168, 256>>>(x, Q, En, Xthi, Xtlo,
                              W1, W1hi, W1lo, W2, W2hi, W2lo, W3, W3hi, W3lo);
    buildG_kernel<<<128, 256>>>(x, Ghi, Glo);

    // 2) V = En .* (G @ Xt^T) - pos  (split output)
    vgemm_kernel<<<dim3(2, 4, 16), 256, SMEM128>>>(Ghi, Glo, Xthi, Xtlo, En, x, Vhi, Vlo);

    // 3) layer 1
    gemm_ps_kernel<128><<<dim3(NH/128, MROWS/128), 256, SMEM128>>>(
        Vhi, Vlo, W1hi, W1lo, b1, Y1, VDIM, NH);
    stats_partial_kernel<<<dim3(NH/32, RS), 256>>>(Y1, MROWS, NH, pS, pS2);
    stats_final_kernel<<<NH/8, 256>>>(pS, pS2, g1, bt1, MROWS, NH, scale, shift);
    bnconvert_kernel<<<(MROWS*NH/4 + 255)/256, 256>>>(Y1, scale, shift, Axhi, Axlo, MROWS*NH/4, NH/4);

    // 4) layer 2
    gemm_ps_kernel<128><<<dim3(NH/128, MROWS/128), 256, SMEM128>>>(
        Axhi, Axlo, W2hi, W2lo, b2, Y2, NH, NH);
    stats_partial_kernel<<<dim3(NH/32, RS), 256>>>(Y2, MROWS, NH, pS, pS2);
    stats_final_kernel<<<NH/8, 256>>>(pS, pS2, g2, bt2, MROWS, NH, scale, shift);
    bnconvert_kernel<<<(MROWS*NH/4 + 255)/256, 256>>>(Y2, scale, shift, Axhi, Axlo, MROWS*NH/4, NH/4);

    // 5) layer 3
    gemm_ps_kernel<64><<<dim3(NO/64, MROWS/128), 256, SMEM64>>>(
        Axhi, Axlo, W3hi, W3lo, b3, Y3, NH, NO);
    stats_partial_kernel<<<dim3(NO/32, RS), 256>>>(Y3, MROWS, NO, pS, pS2);
    stats_final_kernel<<<NO/8, 256>>>(pS, pS2, g3, bt3, MROWS, NO, scale, shift);

    // 6) final BN apply -> out
    int total4 = MROWS * NO / 4;
    bnapply_kernel<<<(total4 + 255)/256, 256>>>(Y3, scale, shift, out, total4, NO/4);
}

// round 6
// speedup vs baseline: 2.8337x; 1.1785x over previous
#include <cuda_runtime.h>
#include <cuda_bf16.h>
#include <cstdint>
#include <math.h>

#define BATCH 16
#define SEQ   512
#define NI    32
#define NHEAD 8
#define NH    512
#define NO    64
#define MROWS (BATCH*SEQ)      // 8192
#define VDIM  (NHEAD*NI)       // 256
#define EPSV  1e-5f
#define SLOPE 0.05f
#define NPART 64               // per-m-block stats partials (MROWS/128)

// ---------------- scratch ----------------
__device__ float    g_En  [16*8*512];
__device__ uint32_t g_Xthi[(size_t)16*256*256], g_Xtlo[(size_t)16*256*256];
__device__ uint32_t g_Ghi [(size_t)16*512*256], g_Glo [(size_t)16*512*256];
__device__ uint32_t g_Vhi [(size_t)8192*128],   g_Vlo [(size_t)8192*128];
__device__ uint32_t g_W1hi[512*128], g_W1lo[512*128];
__device__ uint32_t g_W2hi[512*256], g_W2lo[512*256];
__device__ uint32_t g_W3hi[64*256],  g_W3lo[64*256];
__device__ uint32_t g_Axhi[(size_t)8192*256],   g_Axlo[(size_t)8192*256];
__device__ float g_Y1[(size_t)MROWS * NH];
__device__ float g_Y2[(size_t)MROWS * NH];
__device__ float g_Y3[(size_t)MROWS * NO];
__device__ float g_pS [NPART * NH];
__device__ float g_pS2[NPART * NH];
__device__ float g_scale[NH];
__device__ float g_shift[NH];

// ---------------- helpers ----------------
__device__ __forceinline__ void split_pair(float v0, float v1, uint32_t& hi, uint32_t& lo) {
    __nv_bfloat16 h0 = __float2bfloat16(v0);
    __nv_bfloat16 h1 = __float2bfloat16(v1);
    float r0 = v0 - __bfloat162float(h0);
    float r1 = v1 - __bfloat162float(h1);
    __nv_bfloat16 l0 = __float2bfloat16(r0);
    __nv_bfloat16 l1 = __float2bfloat16(r1);
    hi = ((uint32_t)__bfloat16_as_ushort(h1) << 16) | __bfloat16_as_ushort(h0);
    lo = ((uint32_t)__bfloat16_as_ushort(l1) << 16) | __bfloat16_as_ushort(l0);
}

__device__ __forceinline__ void mma_bf16(float* d, const uint32_t* a, const uint32_t* b) {
    asm volatile(
        "mma.sync.aligned.m16n8k16.row.col.f32.bf16.bf16.f32 "
        "{%0,%1,%2,%3}, {%4,%5,%6,%7}, {%8,%9}, {%0,%1,%2,%3};"
        : "+f"(d[0]), "+f"(d[1]), "+f"(d[2]), "+f"(d[3])
        : "r"(a[0]), "r"(a[1]), "r"(a[2]), "r"(a[3]), "r"(b[0]), "r"(b[1]));
}

__device__ __forceinline__ uint32_t smem_u32(const void* p) {
    uint32_t a;
    asm("{ .reg .u64 t; cvta.to.shared.u64 t, %1; cvt.u32.u64 %0, t; }" : "=r"(a) : "l"(p));
    return a;
}
__device__ __forceinline__ void cp_async16(uint32_t saddr, const void* gptr) {
    asm volatile("cp.async.cg.shared.global [%0], [%1], 16;" :: "r"(saddr), "l"(gptr));
}
#define CP_COMMIT() asm volatile("cp.async.commit_group;" ::: "memory")
#define CP_WAIT1()  asm volatile("cp.async.wait_group 1;" ::: "memory")
#define CP_WAIT0()  asm volatile("cp.async.wait_group 0;" ::: "memory")

// ---------------- prep: En tables, Xt build, W split ----------------
__global__ void __launch_bounds__(256) prep_kernel(
    const float* __restrict__ x, const float* __restrict__ Q,
    float* __restrict__ En,
    uint32_t* __restrict__ Xthi, uint32_t* __restrict__ Xtlo,
    const float* __restrict__ W1, uint32_t* __restrict__ W1hi, uint32_t* __restrict__ W1lo,
    const float* __restrict__ W2, uint32_t* __restrict__ W2hi, uint32_t* __restrict__ W2lo,
    const float* __restrict__ W3, uint32_t* __restrict__ W3hi, uint32_t* __restrict__ W3lo)
{
    const int blk = blockIdx.x;
    const int tid = threadIdx.x;

    if (blk >= 64) {
        int widx = blk - 64;
        const float* src; uint32_t* hi; uint32_t* lo; int base;
        if (widx < 32)      { src = W1; hi = W1hi; lo = W1lo; base = widx * 2048; }
        else if (widx < 96) { src = W2; hi = W2hi; lo = W2lo; base = (widx - 32) * 2048; }
        else                { src = W3; hi = W3hi; lo = W3lo; base = (widx - 96) * 2048; }
        int p = base + tid;
        #pragma unroll
        for (int j = 0; j < 8; j++, p += 256) {
            float2 v = ((const float2*)src)[p];
            uint32_t h, l; split_pair(v.x, v.y, h, l);
            hi[p] = h; lo[p] = l;
        }
        return;
    }

    const int b = blk >> 2, chunk = blk & 3;

    __shared__ float sEm[8][128];
    __shared__ float sQ[8][4];
    __shared__ uint32_t shi[256][8], slo[256][8];

    if (tid < 8) {
        float a = Q[tid*3+0], bq = Q[tid*3+1], cq = Q[tid*3+2];
        sQ[tid][0] = a; sQ[tid][1] = bq; sQ[tid][2] = cq;
        sQ[tid][3] = a*a + bq*bq + cq*cq;
    }
    __syncthreads();

    if (tid < 128) {
        int m = chunk*128 + tid;
        const float* xp = x + ((size_t)b*512 + m)*32;
        float px = xp[0], py = xp[1], pz = xp[2];
        #pragma unroll
        for (int h = 0; h < 8; h++) {
            float dot = px*sQ[h][0] + py*sQ[h][1] + pz*sQ[h][2];
            float em = __expf(-2.f*dot);
            float en = __expf(2.f*dot - sQ[h][3]);
            sEm[h][tid] = em;
            En[((size_t)b*8 + h)*512 + m] = en;
        }
    }
    __syncthreads();

    const int c = tid, h = c >> 5, i = c & 31;
    for (int grp = 0; grp < 8; grp++) {
        #pragma unroll
        for (int j = 0; j < 8; j++) {
            int mloc = (grp*8 + j)*2;
            int m = chunk*128 + mloc;
            float v0 = sEm[h][mloc]   * x[((size_t)b*512 + m  )*32 + i];
            float v1 = sEm[h][mloc+1] * x[((size_t)b*512 + m+1)*32 + i];
            uint32_t hh, ll; split_pair(v0, v1, hh, ll);
            shi[c][j] = hh; slo[c][j] = ll;
        }
        __syncthreads();
        int cc = tid >> 3, j2 = tid & 7;
        #pragma unroll
        for (int rep = 0; rep < 8; rep++) {
            int ccc = cc + rep*32;
            size_t addr = ((size_t)b*256 + ccc)*256 + chunk*64 + grp*8 + j2;
            Xthi[addr] = shi[ccc][j2];
            Xtlo[addr] = slo[ccc][j2];
        }
        __syncthreads();
    }
}

// ---------------- buildG ----------------
__global__ void __launch_bounds__(256) buildG_kernel(
    const float* __restrict__ x, uint32_t* __restrict__ Ghi, uint32_t* __restrict__ Glo)
{
    const int b  = blockIdx.x >> 3, nt = blockIdx.x & 7;
    const int tid = threadIdx.x;
    const int n = tid & 63, mq = tid >> 6;

    __shared__ float pn3[64][5];
    __shared__ float pm3[128][4];

    if (tid < 64) {
        const float* xp = x + ((size_t)b*512 + nt*64 + tid)*32;
        pn3[tid][0] = xp[0]; pn3[tid][1] = xp[1]; pn3[tid][2] = xp[2];
    }

    for (int mc = 0; mc < 4; mc++) {
        __syncthreads();
        if (tid < 128) {
            const float* xp = x + ((size_t)b*512 + mc*128 + tid)*32;
            pm3[tid][0] = xp[0]; pm3[tid][1] = xp[1]; pm3[tid][2] = xp[2];
        }
        __syncthreads();
        float px = pn3[n][0], py = pn3[n][1], pz = pn3[n][2];
        uint32_t outh[16], outl[16];
        #pragma unroll
        for (int j = 0; j < 16; j++) {
            int ml = mq*32 + j*2;
            float dx0 = px - pm3[ml][0],   dy0 = py - pm3[ml][1],   dz0 = pz - pm3[ml][2];
            float dx1 = px - pm3[ml+1][0], dy1 = py - pm3[ml+1][1], dz1 = pz - pm3[ml+1][2];
            float e0 = __expf(-(dx0*dx0 + dy0*dy0 + dz0*dz0));
            float e1 = __expf(-(dx1*dx1 + dy1*dy1 + dz1*dz1));
            split_pair(e0, e1, outh[j], outl[j]);
        }
        size_t base = ((size_t)b*512 + nt*64 + n)*256 + mc*64 + mq*16;
        #pragma unroll
        for (int j4 = 0; j4 < 4; j4++) {
            ((uint4*)(Ghi + base))[j4] = make_uint4(outh[j4*4], outh[j4*4+1], outh[j4*4+2], outh[j4*4+3]);
            ((uint4*)(Glo + base))[j4] = make_uint4(outl[j4*4], outl[j4*4+1], outl[j4*4+2], outl[j4*4+3]);
        }
    }
}

// ================= GEMM machinery =================
#define RSU 20   // u32 row stride; 80B = 5x16B keeps cp.async 16B alignment

// ---------------- vgemm: V = En .* (G @ Xt^T) - pos, TN=64 ----------------
__global__ void __launch_bounds__(256, 2) vgemm_kernel(
    const uint32_t* __restrict__ Ghi, const uint32_t* __restrict__ Glo,
    const uint32_t* __restrict__ Bhi_g, const uint32_t* __restrict__ Blo_g,
    const float* __restrict__ En, const float* __restrict__ x,
    uint32_t* __restrict__ Vhi, uint32_t* __restrict__ Vlo)
{
    constexpr int TN = 64, NFRAG = TN/16, KE = 512, K2 = KE/2;
    extern __shared__ uint32_t smem_u[];
    const uint32_t sbase = smem_u32(smem_u);
    const uint32_t sAh = sbase;
    const uint32_t sAl = sAh + 2*128*RSU*4;
    const uint32_t sBh = sAl + 2*128*RSU*4;
    const uint32_t sBl = sBh + 2*TN*RSU*4;

    const int tid = threadIdx.x, wid = tid >> 5, lane = tid & 31;
    const int wm = (wid >> 1) * 32, wn = (wid & 1) * (TN/2);
    const int l4 = lane >> 2, lk = lane & 3;
    const int b = blockIdx.z;
    const int m0 = blockIdx.y * 128, c0 = blockIdx.x * TN;

    const uint32_t* Ah_g = Ghi + (size_t)b*512*K2;
    const uint32_t* Al_g = Glo + (size_t)b*512*K2;
    const uint32_t* Bh_g = Bhi_g + (size_t)b*256*K2;
    const uint32_t* Bl_g = Blo_g + (size_t)b*256*K2;

    float acc[2][NFRAG][4];
    #pragma unroll
    for (int a = 0; a < 2; a++)
        #pragma unroll
        for (int q = 0; q < NFRAG; q++)
            { acc[a][q][0]=0.f; acc[a][q][1]=0.f; acc[a][q][2]=0.f; acc[a][q][3]=0.f; }

    auto issue = [&](int t) {
        int buf = t & 1;
        #pragma unroll
        for (int j = 0; j < 2; j++) {
            int lin = tid + j*256; int r = lin >> 2, q = lin & 3;
            uint32_t off = (uint32_t)(buf*128*RSU + r*RSU + q*4) * 4;
            size_t ao = (size_t)(m0 + r)*K2 + t*16 + q*4;
            cp_async16(sAh + off, Ah_g + ao);
            cp_async16(sAl + off, Al_g + ao);
        }
        {
            int r = tid >> 2, q = tid & 3;
            uint32_t off = (uint32_t)((tid & 1 ? 0 : 0) + ( ( (tid>>2) ) *0));
            (void)off;
            uint32_t offb = (uint32_t)((t & 1)*TN*RSU + (r & 63)*RSU + q*4) * 4;
            if (r < TN) {
                size_t bo = (size_t)(c0 + r)*K2 + t*16 + q*4;
                cp_async16(sBh + offb, Bh_g + bo);
                cp_async16(sBl + offb, Bl_g + bo);
            }
        }
        CP_COMMIT();
    };

    auto compute = [&](int buf) {
        const uint32_t* Ah = smem_u + buf*128*RSU;
        const uint32_t* Al = smem_u + 2*128*RSU + buf*128*RSU;
        const uint32_t* Bh = smem_u + 4*128*RSU + buf*TN*RSU;
        const uint32_t* Bl = smem_u + 4*128*RSU + 2*TN*RSU + buf*TN*RSU;
        #pragma unroll
        for (int kk = 0; kk < 2; kk++) {
            uint32_t ah[2][4], al[2][4];
            #pragma unroll
            for (int mi = 0; mi < 2; mi++) {
                int base = (wm + mi*16 + l4)*RSU + kk*8 + lk;
                ah[mi][0] = Ah[base];        ah[mi][1] = Ah[base + 8*RSU];
                ah[mi][2] = Ah[base + 4];    ah[mi][3] = Ah[base + 8*RSU + 4];
                al[mi][0] = Al[base];        al[mi][1] = Al[base + 8*RSU];
                al[mi][2] = Al[base + 4];    al[mi][3] = Al[base + 8*RSU + 4];
            }
            #pragma unroll
            for (int ni = 0; ni < NFRAG; ni++) {
                int bbase = (wn + ni*8 + l4)*RSU + kk*8 + lk;
                uint32_t bh[2] = {Bh[bbase], Bh[bbase + 4]};
                uint32_t bl[2] = {Bl[bbase], Bl[bbase + 4]};
                #pragma unroll
                for (int mi = 0; mi < 2; mi++) {
                    mma_bf16(acc[mi][ni], ah[mi], bh);
                    mma_bf16(acc[mi][ni], ah[mi], bl);
                    mma_bf16(acc[mi][ni], al[mi], bh);
                }
            }
        }
    };

    const int T = KE / 32;
    issue(0);
    for (int t = 0; t < T; t++) {
        if (t + 1 < T) { issue(t + 1); CP_WAIT1(); } else { CP_WAIT0(); }
        __syncthreads();
        compute(t & 1);
        __syncthreads();
    }

    // epilogue: scale by En, subtract pos for i<3, split to bf16
    #pragma unroll
    for (int mi = 0; mi < 2; mi++) {
        #pragma unroll
        for (int ni = 0; ni < NFRAG; ni++) {
            int n0 = m0 + wm + mi*16 + l4;
            int cc = c0 + wn + ni*8 + lk*2;
            int h = cc >> 5, il = cc & 31;
            float en0 = En[((size_t)b*8 + h)*512 + n0];
            float en1 = En[((size_t)b*8 + h)*512 + n0 + 8];
            float v00 = acc[mi][ni][0]*en0, v01 = acc[mi][ni][1]*en0;
            float v10 = acc[mi][ni][2]*en1, v11 = acc[mi][ni][3]*en1;
            if (il < 3) {
                v00 -= x[((size_t)b*512 + n0  )*32 + il];
                v10 -= x[((size_t)b*512 + n0+8)*32 + il];
            }
            if (il + 1 < 3) {
                v01 -= x[((size_t)b*512 + n0  )*32 + il + 1];
                v11 -= x[((size_t)b*512 + n0+8)*32 + il + 1];
            }
            uint32_t h0, l0, h1, l1;
            split_pair(v00, v01, h0, l0);
            split_pair(v10, v11, h1, l1);
            size_t r0 = ((size_t)b*512 + n0)*128 + (cc >> 1);
            size_t r1 = ((size_t)b*512 + n0 + 8)*128 + (cc >> 1);
            Vhi[r0] = h0; Vlo[r0] = l0;
            Vhi[r1] = h1; Vlo[r1] = l1;
        }
    }
}

// ---------------- gemm_ps + fused column stats ----------------
// Y[m][c] = bias[c] + sum_k A[m][k]*B[c][k]; writes pS/pS2 per m-block partials
template<int TN>
__global__ void __launch_bounds__(256, 2) gemm_ps_kernel(
    const uint32_t* __restrict__ Ah_g, const uint32_t* __restrict__ Al_g,
    const uint32_t* __restrict__ Bh_g, const uint32_t* __restrict__ Bl_g,
    const float* __restrict__ bias, float* __restrict__ Y,
    float* __restrict__ pS, float* __restrict__ pS2, int K, int C)
{
    constexpr int NFRAG = TN/16;
    constexpr int BLD = TN/64;   // uint4 cp.async per thread for B per component
    extern __shared__ uint32_t smem_u[];
    const uint32_t sbase = smem_u32(smem_u);
    const uint32_t sAh = sbase;
    const uint32_t sAl = sAh + 2*128*RSU*4;
    const uint32_t sBh = sAl + 2*128*RSU*4;
    const uint32_t sBl = sBh + 2*TN*RSU*4;

    const int tid = threadIdx.x, wid = tid >> 5, lane = tid & 31;
    const int wm = (wid >> 1) * 32, wn = (wid & 1) * (TN/2);
    const int mw = wid >> 1;
    const int l4 = lane >> 2, lk = lane & 3;
    const int m0 = blockIdx.y * 128, c0 = blockIdx.x * TN;
    const int K2 = K >> 1;

    float acc[2][NFRAG][4];
    #pragma unroll
    for (int a = 0; a < 2; a++)
        #pragma unroll
        for (int q = 0; q < NFRAG; q++)
            { acc[a][q][0]=0.f; acc[a][q][1]=0.f; acc[a][q][2]=0.f; acc[a][q][3]=0.f; }

    auto issue = [&](int t) {
        int buf = t & 1;
        #pragma unroll
        for (int j = 0; j < 2; j++) {
            int lin = tid + j*256; int r = lin >> 2, q = lin & 3;
            uint32_t off = (uint32_t)(buf*128*RSU + r*RSU + q*4) * 4;
            size_t ao = (size_t)(m0 + r)*K2 + t*16 + q*4;
            cp_async16(sAh + off, Ah_g + ao);
            cp_async16(sAl + off, Al_g + ao);
        }
        #pragma unroll
        for (int j = 0; j < BLD; j++) {
            int lin = tid + j*256; int r = lin >> 2, q = lin & 3;
            uint32_t off = (uint32_t)(buf*TN*RSU + r*RSU + q*4) * 4;
            size_t bo = (size_t)(c0 + r)*K2 + t*16 + q*4;
            cp_async16(sBh + off, Bh_g + bo);
            cp_async16(sBl + off, Bl_g + bo);
        }
        CP_COMMIT();
    };

    auto compute = [&](int buf) {
        const uint32_t* Ah = smem_u + buf*128*RSU;
        const uint32_t* Al = smem_u + 2*128*RSU + buf*128*RSU;
        const uint32_t* Bh = smem_u + 4*128*RSU + buf*TN*RSU;
        const uint32_t* Bl = smem_u + 4*128*RSU + 2*TN*RSU + buf*TN*RSU;
        #pragma unroll
        for (int kk = 0; kk < 2; kk++) {
            uint32_t ah[2][4], al[2][4];
            #pragma unroll
            for (int mi = 0; mi < 2; mi++) {
                int base = (wm + mi*16 + l4)*RSU + kk*8 + lk;
                ah[mi][0] = Ah[base];        ah[mi][1] = Ah[base + 8*RSU];
                ah[mi][2] = Ah[base + 4];    ah[mi][3] = Ah[base + 8*RSU + 4];
                al[mi][0] = Al[base];        al[mi][1] = Al[base + 8*RSU];
                al[mi][2] = Al[base + 4];    al[mi][3] = Al[base + 8*RSU + 4];
            }
            #pragma unroll
            for (int ni = 0; ni < NFRAG; ni++) {
                int bbase = (wn + ni*8 + l4)*RSU + kk*8 + lk;
                uint32_t bh[2] = {Bh[bbase], Bh[bbase + 4]};
                uint32_t bl[2] = {Bl[bbase], Bl[bbase + 4]};
                #pragma unroll
                for (int mi = 0; mi < 2; mi++) {
                    mma_bf16(acc[mi][ni], ah[mi], bh);
                    mma_bf16(acc[mi][ni], ah[mi], bl);
                    mma_bf16(acc[mi][ni], al[mi], bh);
                }
            }
        }
    };

    const int T = K / 32;
    issue(0);
    for (int t = 0; t < T; t++) {
        if (t + 1 < T) { issue(t + 1); CP_WAIT1(); } else { CP_WAIT0(); }
        __syncthreads();
        compute(t & 1);
        __syncthreads();
    }

    // ---- epilogue: store Y + fused column stats ----
    float* sbufS  = (float*)smem_u;         // [4][TN]
    float* sbufS2 = sbufS + 4*TN;

    #pragma unroll
    for (int ni = 0; ni < NFRAG; ni++) {
        int col = c0 + wn + ni*8 + lk*2;
        float2 b2 = *(const float2*)(bias + col);
        float s0 = 0.f, s1 = 0.f, q0 = 0.f, q1 = 0.f;
        #pragma unroll
        for (int mi = 0; mi < 2; mi++) {
            int row = m0 + wm + mi*16 + l4;
            float e0 = acc[mi][ni][0] + b2.x;
            float e1 = acc[mi][ni][1] + b2.y;
            float e2 = acc[mi][ni][2] + b2.x;
            float e3 = acc[mi][ni][3] + b2.y;
            *(float2*)(Y + (size_t)row * C + col)       = make_float2(e0, e1);
            *(float2*)(Y + (size_t)(row + 8) * C + col) = make_float2(e2, e3);
            s0 += e0 + e2; s1 += e1 + e3;
            q0 += e0*e0 + e2*e2; q1 += e1*e1 + e3*e3;
        }
        #pragma unroll
        for (int off = 16; off >= 4; off >>= 1) {
            s0 += __shfl_down_sync(0xffffffffu, s0, off);
            s1 += __shfl_down_sync(0xffffffffu, s1, off);
            q0 += __shfl_down_sync(0xffffffffu, q0, off);
            q1 += __shfl_down_sync(0xffffffffu, q1, off);
        }
        if (lane < 4) {
            int cb = wn + ni*8 + lk*2;
            sbufS [mw*TN + cb]     = s0;
            sbufS [mw*TN + cb + 1] = s1;
            sbufS2[mw*TN + cb]     = q0;
            sbufS2[mw*TN + cb + 1] = q1;
        }
    }
    __syncthreads();
    if (tid < TN) {
        float s = sbufS [tid] + sbufS [TN + tid] + sbufS [2*TN + tid] + sbufS [3*TN + tid];
        float q = sbufS2[tid] + sbufS2[TN + tid] + sbufS2[2*TN + tid] + sbufS2[3*TN + tid];
        pS [blockIdx.y * C + c0 + tid] = s;
        pS2[blockIdx.y * C + c0 + tid] = q;
    }
}

// ---------------- stats_final: reduce 64 partials per column ----------------
__global__ void __launch_bounds__(256) stats_final_kernel(
    const float* __restrict__ pS, const float* __restrict__ pS2,
    const float* __restrict__ g, const float* __restrict__ bt,
    int M, int C, float* __restrict__ scale, float* __restrict__ shift)
{
    const int c = blockIdx.x * 8 + (threadIdx.x >> 5);
    const int j = threadIdx.x & 31;
    float s  = pS [j * C + c] + pS [(j + 32) * C + c];
    float s2 = pS2[j * C + c] + pS2[(j + 32) * C + c];
    #pragma unroll
    for (int off = 16; off > 0; off >>= 1) {
        s  += __shfl_down_sync(0xffffffffu, s,  off);
        s2 += __shfl_down_sync(0xffffffffu, s2, off);
    }
    if (j == 0) {
        float invM = 1.f / (float)M;
        float mean = s * invM;
        float var  = fmaf(-mean, mean, s2 * invM);
        float inv  = rsqrtf(var + EPSV);
        float scv  = g[c] * inv;
        scale[c] = scv;
        shift[c] = fmaf(-mean, scv, bt[c]);
    }
}

// ---------------- bnconvert ----------------
__global__ void __launch_bounds__(256) bnconvert_kernel(
    const float* __restrict__ Y, const float* __restrict__ scale,
    const float* __restrict__ shift, uint32_t* __restrict__ hi, uint32_t* __restrict__ lo,
    int total4, int C4)
{
    int idx = blockIdx.x * blockDim.x + threadIdx.x;
    if (idx >= total4) return;
    int c4 = idx % C4;
    float4 y  = ((const float4*)Y)[idx];
    float4 sc = ((const float4*)scale)[c4];
    float4 sh = ((const float4*)shift)[c4];
    float v[4];
    v[0] = fmaf(y.x, sc.x, sh.x); v[1] = fmaf(y.y, sc.y, sh.y);
    v[2] = fmaf(y.z, sc.z, sh.z); v[3] = fmaf(y.w, sc.w, sh.w);
    #pragma unroll
    for (int q = 0; q < 4; q++) v[q] = v[q] > 0.f ? v[q] : v[q] * SLOPE;
    uint32_t h0, l0, h1, l1;
    split_pair(v[0], v[1], h0, l0);
    split_pair(v[2], v[3], h1, l1);
    ((uint2*)hi)[idx] = make_uint2(h0, h1);
    ((uint2*)lo)[idx] = make_uint2(l0, l1);
}

// ---------------- final BN apply ----------------
__global__ void __launch_bounds__(256) bnapply_kernel(
    const float* __restrict__ Y, const float* __restrict__ scale,
    const float* __restrict__ shift, float* __restrict__ out, int total4, int C4)
{
    int idx = blockIdx.x * blockDim.x + threadIdx.x;
    if (idx >= total4) return;
    int c4 = idx % C4;
    float4 y  = ((const float4*)Y)[idx];
    float4 sc = ((const float4*)scale)[c4];
    float4 sh = ((const float4*)shift)[c4];
    float4 o;
    o.x = fmaf(y.x, sc.x, sh.x);
    o.y = fmaf(y.y, sc.y, sh.y);
    o.z = fmaf(y.z, sc.z, sh.z);
    o.w = fmaf(y.w, sc.w, sh.w);
    ((float4*)out)[idx] = o;
}

// ---------------- host ----------------
extern "C" void kernel_launch(void* const* d_in, const int* in_sizes, int n_in,
                              void* d_out, int out_size)
{
    const float* x   = (const float*)d_in[0];
    const float* Q   = (const float*)d_in[1];
    const float* W1  = (const float*)d_in[2];
    const float* b1  = (const float*)d_in[3];
    const float* g1  = (const float*)d_in[4];
    const float* bt1 = (const float*)d_in[5];
    const float* W2  = (const float*)d_in[6];
    const float* b2  = (const float*)d_in[7];
    const float* g2  = (const float*)d_in[8];
    const float* bt2 = (const float*)d_in[9];
    const float* W3  = (const float*)d_in[10];
    const float* b3  = (const float*)d_in[11];
    const float* g3  = (const float*)d_in[12];
    const float* bt3 = (const float*)d_in[13];
    float* out = (float*)d_out;

    float *En, *Y1, *Y2, *Y3, *pS, *pS2, *scale, *shift;
    uint32_t *Xthi, *Xtlo, *Ghi, *Glo, *Vhi, *Vlo, *Axhi, *Axlo;
    uint32_t *W1hi, *W1lo, *W2hi, *W2lo, *W3hi, *W3lo;
    cudaGetSymbolAddress((void**)&En,   g_En);
    cudaGetSymbolAddress((void**)&Xthi, g_Xthi);  cudaGetSymbolAddress((void**)&Xtlo, g_Xtlo);
    cudaGetSymbolAddress((void**)&Ghi,  g_Ghi);   cudaGetSymbolAddress((void**)&Glo,  g_Glo);
    cudaGetSymbolAddress((void**)&Vhi,  g_Vhi);   cudaGetSymbolAddress((void**)&Vlo,  g_Vlo);
    cudaGetSymbolAddress((void**)&Axhi, g_Axhi);  cudaGetSymbolAddress((void**)&Axlo, g_Axlo);
    cudaGetSymbolAddress((void**)&W1hi, g_W1hi);  cudaGetSymbolAddress((void**)&W1lo, g_W1lo);
    cudaGetSymbolAddress((void**)&W2hi, g_W2hi);  cudaGetSymbolAddress((void**)&W2lo, g_W2lo);
    cudaGetSymbolAddress((void**)&W3hi, g_W3hi);  cudaGetSymbolAddress((void**)&W3lo, g_W3lo);
    cudaGetSymbolAddress((void**)&Y1, g_Y1);
    cudaGetSymbolAddress((void**)&Y2, g_Y2);
    cudaGetSymbolAddress((void**)&Y3, g_Y3);
    cudaGetSymbolAddress((void**)&pS, g_pS);      cudaGetSymbolAddress((void**)&pS2, g_pS2);
    cudaGetSymbolAddress((void**)&scale, g_scale); cudaGetSymbolAddress((void**)&shift, g_shift);

    const int SMEM128 = RSU * (2*128 + 2*128) * 2 * 4;   // 81920 B
    const int SMEM64  = RSU * (2*128 + 2*64)  * 2 * 4;   // 61440 B
    cudaFuncSetAttribute(vgemm_kernel,        cudaFuncAttributeMaxDynamicSharedMemorySize, SMEM64);
    cudaFuncSetAttribute(gemm_ps_kernel<128>, cudaFuncAttributeMaxDynamicSharedMemorySize, SMEM128);
    cudaFuncSetAttribute(gemm_ps_kernel<64>,  cudaFuncAttributeMaxDynamicSharedMemorySize, SMEM64);

    // 1) prep + buildG
    prep_kernel<<<168, 256>>>(x, Q, En, Xthi, Xtlo,
                              W1, W1hi, W1lo, W2, W2hi, W2lo, W3, W3hi, W3lo);
    buildG_kernel<<<128, 256>>>(x, Ghi, Glo);

    // 2) V = En .* (G @ Xt^T) - pos
    vgemm_kernel<<<dim3(4, 4, 16), 256, SMEM64>>>(Ghi, Glo, Xthi, Xtlo, En, x, Vhi, Vlo);

    // 3) layer 1 (stats fused)
    gemm_ps_kernel<128><<<dim3(NH/128, MROWS/128), 256, SMEM128>>>(
        Vhi, Vlo, W1hi, W1lo, b1, Y1, pS, pS2, VDIM, NH);
    stats_final_kernel<<<NH/8, 256>>>(pS, pS2, g1, bt1, MROWS, NH, scale, shift);
    bnconvert_kernel<<<(MROWS*NH/4 + 255)/256, 256>>>(Y1, scale, shift, Axhi, Axlo, MROWS*NH/4, NH/4);

    // 4) layer 2 (stats fused)
    gemm_ps_kernel<128><<<dim3(NH/128, MROWS/128), 256, SMEM128>>>(
        Axhi, Axlo, W2hi, W2lo, b2, Y2, pS, pS2, NH, NH);
    stats_final_kernel<<<NH/8, 256>>>(pS, pS2, g2, bt2, MROWS, NH, scale, shift);
    bnconvert_kernel<<<(MROWS*NH/4 + 255)/256, 256>>>(Y2, scale, shift, Axhi, Axlo, MROWS*NH/4, NH/4);

    // 5) layer 3 (stats fused)
    gemm_ps_kernel<64><<<dim3(NO/64, MROWS/128), 256, SMEM64>>>(
        Axhi, Axlo, W3hi, W3lo, b3, Y3, pS, pS2, NH, NO);
    stats_final_kernel<<<NO/8, 256>>>(pS, pS2, g3, bt3, MROWS, NO, scale, shift);

    // 6) final BN apply -> out
    int total4 = MROWS * NO / 4;
    bnapply_kernel<<<(total4 + 255)/256, 256>>>(Y3, scale, shift, out, total4, NO/4);
}